// round 1
// baseline (speedup 1.0000x reference)
#include <cuda_runtime.h>

// Problem constants
#define BB   256   // batch
#define TT   32    // T-1 timesteps
#define ENCD 128
#define DECD 128
#define G4   512   // 4*DEC

// Scratch (device globals: no allocation allowed)
__device__ float g_E1[BB * TT * ENCD];       // [B][T][ENC] : enc @ W1e^T + b1
__device__ float g_W1T[256 * 128];           // [k=256][j=128] : W1_hc transposed
__device__ float g_WhhT[128 * 512];          // [k=128][r=512] : W_hh transposed

__device__ __forceinline__ float fast_tanh(float x) {
    float y;
    asm("tanh.approx.f32 %0, %1;" : "=f"(y) : "f"(x));
    return y;
}

// ---------------------------------------------------------------------------
// Prep kernel: E1 precompute (blocks 0..255), W_hh transpose (256..263),
// W1_hc transpose (264..271).
// ---------------------------------------------------------------------------
__global__ void __launch_bounds__(128)
prep_kernel(const float* __restrict__ enc,   // [B,T,ENC]
            const float* __restrict__ W1,    // [ENC, 384] rows: [hc(256) | enc(128)]
            const float* __restrict__ b1,    // [ENC]
            const float* __restrict__ Whh)   // [512,128]
{
    int bid = blockIdx.x;
    if (bid < BB) {
        __shared__ float enc_s[TT * ENCD];
        const float* eb = enc + bid * TT * ENCD;
        for (int i = threadIdx.x; i < TT * ENCD; i += blockDim.x)
            enc_s[i] = eb[i];
        __syncthreads();
        int h = threadIdx.x;  // 128 threads, one per hidden unit
        float acc[TT];
        float bb = b1[h];
#pragma unroll
        for (int t = 0; t < TT; t++) acc[t] = bb;
        const float4* wrow = reinterpret_cast<const float4*>(W1 + h * 384 + 256);
#pragma unroll 2
        for (int k4 = 0; k4 < ENCD / 4; k4++) {
            float4 w = wrow[k4];
#pragma unroll
            for (int t = 0; t < TT; t++) {
                float4 e = reinterpret_cast<const float4*>(enc_s + t * ENCD)[k4];
                acc[t] += w.x * e.x + w.y * e.y + w.z * e.z + w.w * e.w;
            }
        }
        float* outp = g_E1 + bid * TT * ENCD;
#pragma unroll
        for (int t = 0; t < TT; t++) outp[t * ENCD + h] = acc[t];
    } else if (bid < 264) {
        // WhhT[k][r] = Whh[r*128 + k]
        int base = (bid - 256) * 8192;
        for (int i = base + threadIdx.x; i < base + 8192; i += 128) {
            int k = i >> 9, r = i & 511;
            g_WhhT[i] = Whh[r * 128 + k];
        }
    } else {
        // W1T[k][j] = W1[j*384 + k]  (hc part, k<256)
        int base = (bid - 264) * 4096;
        for (int i = base + threadIdx.x; i < base + 4096; i += 128) {
            int k = i >> 7, j = i & 127;
            g_W1T[i] = W1[j * 384 + k];
        }
    }
}

// ---------------------------------------------------------------------------
// Main kernel: 128 blocks x 256 threads, 2 batches per block, full 32-step
// recurrence block-local.
// ---------------------------------------------------------------------------
__global__ void __launch_bounds__(256, 1)
decoder_kernel(const float* __restrict__ enc,      // [B,T,ENC]
               const float* __restrict__ yhist,    // [B,T,1]
               const float* __restrict__ W2,       // [1,ENC]
               const float* __restrict__ Wih,      // [512,1]
               const float* __restrict__ bih,      // [512]
               const float* __restrict__ bhh,      // [512]
               const float* __restrict__ fcW,      // [1,129]
               const float* __restrict__ fcb,      // [1]
               const float* __restrict__ fcfW,     // [1,256]
               const float* __restrict__ fcfb,     // [1]
               float* __restrict__ out)            // [B,1]
{
    extern __shared__ float sm[];
    float* sW1T   = sm;                // 32768  [k=256][j=128]
    float* sE1    = sW1T + 32768;      // 8192   [g=2][t=32][h=128]
    float* sEnc   = sE1 + 8192;        // 8192   [g=2][t=32][e=128]
    float* shc    = sEnc + 8192;       // 512    [g=2][h(0..127), c(128..255)]
    float* su     = shc + 512;         // 256    [g=2][128]
    float* slog   = su + 256;          // 64     [g=2][32] logits -> attn
    float* sctx   = slog + 64;         // 256    [g=2][128]
    float* sgates = sctx + 256;        // 1024   [g=2][512]
    float* sWih   = sgates + 1024;     // 512
    float* sbias  = sWih + 512;        // 512
    float* sfc    = sbias + 512;       // 129
    float* sfcf   = sfc + 129;         // 256
    float* sY     = sfcf + 256;        // 2

    const int tid  = threadIdx.x;
    const int b0   = blockIdx.x * 2;
    const int lane = tid & 31;
    const int warp = tid >> 5;
    const int g    = tid >> 7;   // batch-in-block (0/1)
    const int j    = tid & 127;  // hidden index

    // ---- load phase ----
    for (int i = tid; i < 32768 / 4; i += 256)
        reinterpret_cast<float4*>(sW1T)[i] =
            reinterpret_cast<const float4*>(g_W1T)[i];
    for (int i = tid; i < 8192 / 4; i += 256) {
        reinterpret_cast<float4*>(sE1)[i] =
            reinterpret_cast<const float4*>(g_E1 + (size_t)b0 * TT * ENCD)[i];
        reinterpret_cast<float4*>(sEnc)[i] =
            reinterpret_cast<const float4*>(enc + (size_t)b0 * TT * ENCD)[i];
    }
    for (int i = tid; i < 512; i += 256) {
        sWih[i]  = Wih[i];
        sbias[i] = bih[i] + bhh[i];
        shc[i]   = 0.f;   // h0 = c0 = 0
    }
    if (tid < 129) sfc[tid]  = fcW[tid];
    sfcf[tid] = fcfW[tid];

    // per-lane attn_W2 registers for phase B
    float w2r[4];
#pragma unroll
    for (int m = 0; m < 4; m++) w2r[m] = W2[lane + 32 * m];
    __syncthreads();

    for (int step = 0; step < TT; step++) {
        // ---- A: u[g][j] = sum_k hc[g][k] * W1T[k][j]  (k=256)
        {
            float acc = 0.f;
            const float* hcg = shc + g * 256;
#pragma unroll 4
            for (int k4 = 0; k4 < 64; k4++) {
                float4 h4 = reinterpret_cast<const float4*>(hcg)[k4];
                int k = k4 * 4;
                acc += h4.x * sW1T[(k + 0) * 128 + j];
                acc += h4.y * sW1T[(k + 1) * 128 + j];
                acc += h4.z * sW1T[(k + 2) * 128 + j];
                acc += h4.w * sW1T[(k + 3) * 128 + j];
            }
            su[g * 128 + j] = acc;
        }
        __syncthreads();

        // ---- B: logits[p], p=0..63 (pg = p>>5, pt = p&31)
        {
#pragma unroll
            for (int i = 0; i < 8; i++) {
                int p  = warp + 8 * i;
                int pg = p >> 5, pt = p & 31;
                const float* e1p = sE1 + (pg * 32 + pt) * 128;
                const float* up  = su + pg * 128;
                float s = 0.f;
#pragma unroll
                for (int m = 0; m < 4; m++) {
                    int h = lane + 32 * m;
                    s += fast_tanh(e1p[h] + up[h]) * w2r[m];
                }
#pragma unroll
                for (int o = 16; o > 0; o >>= 1)
                    s += __shfl_xor_sync(0xffffffffu, s, o);
                if (lane == 0) slog[p] = s;
            }
        }
        __syncthreads();

        // ---- C: softmax over t (warps 0,1 = batch 0,1)
        if (warp < 2) {
            float l  = slog[warp * 32 + lane];
            float mx = l;
#pragma unroll
            for (int o = 16; o > 0; o >>= 1)
                mx = fmaxf(mx, __shfl_xor_sync(0xffffffffu, mx, o));
            float e   = expf(l - mx);
            float sum = e;
#pragma unroll
            for (int o = 16; o > 0; o >>= 1)
                sum += __shfl_xor_sync(0xffffffffu, sum, o);
            slog[warp * 32 + lane] = e / sum;
        }
        __syncthreads();

        // ---- D: ctx[g][j] = sum_t attn[g][t] * enc[g][t][j]
        {
            float acc = 0.f;
            const float* ag = slog + g * 32;
            const float* eg = sEnc + g * 32 * 128;
#pragma unroll 8
            for (int t = 0; t < 32; t++)
                acc += ag[t] * eg[t * 128 + j];
            sctx[g * 128 + j] = acc;
        }
        __syncthreads();

        // ---- E: y_tilde[g] = ctx . fcW[0:128] + y_t*fcW[128] + fcb
        if (warp < 2) {
            float s = 0.f;
#pragma unroll
            for (int m = 0; m < 4; m++) {
                int e = lane + 32 * m;
                s += sctx[warp * 128 + e] * sfc[e];
            }
#pragma unroll
            for (int o = 16; o > 0; o >>= 1)
                s += __shfl_xor_sync(0xffffffffu, s, o);
            if (lane == 0) {
                float yt = yhist[(b0 + warp) * TT + step];
                sY[warp] = s + yt * sfc[128] + fcb[0];
            }
        }
        __syncthreads();

        // ---- F: gates. Thread owns rows {2*tid, 2*tid+1} of W_hh, both batches.
        {
            int r0 = tid * 2;
            float y0 = sY[0], y1 = sY[1];
            float a00 = sbias[r0]     + y0 * sWih[r0];
            float a01 = sbias[r0 + 1] + y0 * sWih[r0 + 1];
            float a10 = sbias[r0]     + y1 * sWih[r0];
            float a11 = sbias[r0 + 1] + y1 * sWih[r0 + 1];
            const float2* wt = reinterpret_cast<const float2*>(g_WhhT) + tid;
            const float* h0 = shc;         // h of batch 0
            const float* h1 = shc + 256;   // h of batch 1
#pragma unroll 4
            for (int k4 = 0; k4 < 32; k4++) {
                float4 hv0 = reinterpret_cast<const float4*>(h0)[k4];
                float4 hv1 = reinterpret_cast<const float4*>(h1)[k4];
                float2 w0  = wt[(k4 * 4 + 0) * 256];
                float2 w1  = wt[(k4 * 4 + 1) * 256];
                float2 w2_ = wt[(k4 * 4 + 2) * 256];
                float2 w3  = wt[(k4 * 4 + 3) * 256];
                a00 += hv0.x * w0.x + hv0.y * w1.x + hv0.z * w2_.x + hv0.w * w3.x;
                a01 += hv0.x * w0.y + hv0.y * w1.y + hv0.z * w2_.y + hv0.w * w3.y;
                a10 += hv1.x * w0.x + hv1.y * w1.x + hv1.z * w2_.x + hv1.w * w3.x;
                a11 += hv1.x * w0.y + hv1.y * w1.y + hv1.z * w2_.y + hv1.w * w3.y;
            }
            sgates[r0]           = a00;
            sgates[r0 + 1]       = a01;
            sgates[512 + r0]     = a10;
            sgates[512 + r0 + 1] = a11;
        }
        __syncthreads();

        // ---- G: LSTM cell update (accurate activations)
        {
            float gi = sgates[g * 512 + j];
            float gf = sgates[g * 512 + 128 + j];
            float gg = sgates[g * 512 + 256 + j];
            float go = sgates[g * 512 + 384 + j];
            float c_old = shc[g * 256 + 128 + j];
            float si = 1.f / (1.f + expf(-gi));
            float sf = 1.f / (1.f + expf(-gf));
            float so = 1.f / (1.f + expf(-go));
            float cn = sf * c_old + si * tanhf(gg);
            float hn = so * tanhf(cn);
            shc[g * 256 + 128 + j] = cn;
            shc[g * 256 + j]       = hn;
        }
        __syncthreads();
    }

    // ---- final: out[b] = [h, ctx] . fcfW + fcfb + y_history[b, T-1]
    if (warp < 2) {
        float s = 0.f;
#pragma unroll
        for (int m = 0; m < 8; m++) {
            int e = lane + 32 * m;
            float v = (e < 128) ? shc[warp * 256 + e] : sctx[warp * 128 + (e - 128)];
            s += v * sfcf[e];
        }
#pragma unroll
        for (int o = 16; o > 0; o >>= 1)
            s += __shfl_xor_sync(0xffffffffu, s, o);
        if (lane == 0)
            out[b0 + warp] = s + fcfb[0] + yhist[(b0 + warp) * TT + (TT - 1)];
    }
}

// ---------------------------------------------------------------------------
extern "C" void kernel_launch(void* const* d_in, const int* in_sizes, int n_in,
                              void* d_out, int out_size)
{
    const float* enc  = (const float*)d_in[0];
    const float* yh   = (const float*)d_in[1];
    const float* W1   = (const float*)d_in[2];
    const float* b1   = (const float*)d_in[3];
    const float* W2   = (const float*)d_in[4];
    // d_in[5] = attn_b2 : constant shift, cancels in softmax
    const float* Wih  = (const float*)d_in[6];
    const float* Whh  = (const float*)d_in[7];
    const float* bih  = (const float*)d_in[8];
    const float* bhh  = (const float*)d_in[9];
    const float* fcW  = (const float*)d_in[10];
    const float* fcb  = (const float*)d_in[11];
    const float* fcfW = (const float*)d_in[12];
    const float* fcfb = (const float*)d_in[13];
    float* out = (float*)d_out;

    const size_t smem_floats = 32768 + 8192 + 8192 + 512 + 256 + 64 + 256
                             + 1024 + 512 + 512 + 129 + 256 + 2 + 13; // pad
    const size_t smem = smem_floats * sizeof(float);   // ~211 KB

    cudaFuncSetAttribute(decoder_kernel,
                         cudaFuncAttributeMaxDynamicSharedMemorySize, (int)smem);

    prep_kernel<<<272, 128>>>(enc, W1, b1, Whh);
    decoder_kernel<<<128, 256, smem>>>(enc, yh, W2, Wih, bih, bhh,
                                       fcW, fcb, fcfW, fcfb, out);
}

// round 2
// speedup vs baseline: 1.0569x; 1.0569x over previous
#include <cuda_runtime.h>

// Problem constants
#define BB   256   // batch
#define TT   32    // T-1 timesteps
#define ENCD 128
#define DECD 128

#define W1S  268   // padded row stride (floats) for W1 in smem, conflict-free

// Scratch (device globals: no allocation allowed)
__device__ float  g_E1[BB * TT * ENCD];     // [B][T][ENC] : enc @ W1e^T + b1
__device__ float  g_W1P[128 * W1S];         // [j=128][k=268] row-major, padded
__device__ float4 g_Whh4[32 * 512];         // [k4=32][r=512] -> float4 of Whh[r][4k4..4k4+3]

__device__ __forceinline__ float fast_tanh(float x) {
    float y;
    asm("tanh.approx.f32 %0, %1;" : "=f"(y) : "f"(x));
    return y;
}

// ---------------------------------------------------------------------------
// Prep: E1 precompute (blocks 0..255), Whh repack (256..263), W1 pad (264..271)
// ---------------------------------------------------------------------------
__global__ void __launch_bounds__(128)
prep_kernel(const float* __restrict__ enc,   // [B,T,ENC]
            const float* __restrict__ W1,    // [128, 384] rows: [hc(256) | enc(128)]
            const float* __restrict__ b1,    // [128]
            const float* __restrict__ Whh)   // [512,128]
{
    int bid = blockIdx.x;
    if (bid < BB) {
        __shared__ float enc_s[TT * ENCD];
        const float* eb = enc + bid * TT * ENCD;
        for (int i = threadIdx.x; i < TT * ENCD; i += blockDim.x)
            enc_s[i] = eb[i];
        __syncthreads();
        int h = threadIdx.x;  // one per hidden unit
        float acc[TT];
        float bb = b1[h];
#pragma unroll
        for (int t = 0; t < TT; t++) acc[t] = bb;
        const float4* wrow = reinterpret_cast<const float4*>(W1 + h * 384 + 256);
#pragma unroll 2
        for (int k4 = 0; k4 < ENCD / 4; k4++) {
            float4 w = wrow[k4];
#pragma unroll
            for (int t = 0; t < TT; t++) {
                float4 e = reinterpret_cast<const float4*>(enc_s + t * ENCD)[k4];
                acc[t] += w.x * e.x + w.y * e.y + w.z * e.z + w.w * e.w;
            }
        }
        float* outp = g_E1 + bid * TT * ENCD;
#pragma unroll
        for (int t = 0; t < TT; t++) outp[t * ENCD + h] = acc[t];
    } else if (bid < 264) {
        // Whh4[(k4*512 + r)*4 + m] = Whh[r*128 + 4*k4 + m]
        int base = (bid - 256) * 8192;
        float* dst = reinterpret_cast<float*>(g_Whh4);
        for (int i = base + threadIdx.x; i < base + 8192; i += 128) {
            int k4 = i >> 11;
            int r  = (i >> 2) & 511;
            int m  = i & 3;
            dst[i] = Whh[r * 128 + (k4 << 2) + m];
        }
    } else {
        // W1P[j][k] = W1[j*384+k] for k<256, 0 pad otherwise
        int jbase = (bid - 264) * 16;
        for (int i = threadIdx.x; i < 16 * W1S; i += 128) {
            int j0 = i / W1S, k = i % W1S;
            int j = jbase + j0;
            g_W1P[j * W1S + k] = (k < 256) ? W1[j * 384 + k] : 0.f;
        }
    }
}

// ---------------------------------------------------------------------------
// Main kernel: 128 blocks x 512 threads, 2 batches per block.
// ---------------------------------------------------------------------------
__global__ void __launch_bounds__(512, 1)
decoder_kernel(const float* __restrict__ enc,      // [B,T,ENC]
               const float* __restrict__ yhist,    // [B,T,1]
               const float* __restrict__ W2,       // [1,ENC]
               const float* __restrict__ Wih,      // [512,1]
               const float* __restrict__ bih,      // [512]
               const float* __restrict__ bhh,      // [512]
               const float* __restrict__ fcW,      // [1,129]
               const float* __restrict__ fcb,      // [1]
               const float* __restrict__ fcfW,     // [1,256]
               const float* __restrict__ fcfb,     // [1]
               float* __restrict__ out)            // [B,1]
{
    extern __shared__ float sm[];
    float* sW1    = sm;                 // 34304 [j=128][k=268]
    float* sE1    = sW1 + 34304;        // 8192  [g=2][t=32][h=128]
    float* sEnc   = sE1 + 8192;         // 8192  [g=2][t=32][e=128]
    float* shc    = sEnc + 8192;        // 512   [g=2][h(0..127), c(128..255)]
    float* su     = shc + 512;          // 256   [g=2][128]
    float* slog   = su + 256;           // 64    [g=2][32]
    float* sctx2  = slog + 64;          // 512   [th=2][g=2][128]
    float* sgates = sctx2 + 512;        // 1024  [g=2][512]
    float* sWih   = sgates + 1024;      // 512
    float* sbias  = sWih + 512;         // 512
    float* sfc    = sbias + 512;        // 132
    float* sfcf   = sfc + 132;          // 256
    float* sY     = sfcf + 256;         // 4

    const int tid  = threadIdx.x;
    const int lane = tid & 31;
    const int warp = tid >> 5;
    const int b0   = blockIdx.x * 2;

    // ---- load phase ----
    for (int i = tid; i < 34304 / 4; i += 512)
        reinterpret_cast<float4*>(sW1)[i] =
            reinterpret_cast<const float4*>(g_W1P)[i];
    for (int i = tid; i < 8192 / 4; i += 512) {
        reinterpret_cast<float4*>(sE1)[i] =
            reinterpret_cast<const float4*>(g_E1 + (size_t)b0 * TT * ENCD)[i];
        reinterpret_cast<float4*>(sEnc)[i] =
            reinterpret_cast<const float4*>(enc + (size_t)b0 * TT * ENCD)[i];
    }
    {
        sWih[tid]  = Wih[tid];
        sbias[tid] = bih[tid] + bhh[tid];
        if (tid < 512) {}  // all 512 covered above
    }
    if (tid < 256) shc[tid] = 0.f, shc[256 + tid] = 0.f;
    if (tid < 132) sfc[tid] = (tid < 129) ? fcW[tid] : 0.f;
    if (tid < 256) sfcf[tid] = fcfW[tid];

    // phase B constant: W2 as float4 per lane
    const float4 w2v = reinterpret_cast<const float4*>(W2)[lane];

    // phase A thread coordinates: q = k-quarter, ja = hidden index
    const int qa = lane >> 3;
    const int ja = (warp << 3) | (lane & 7);
    const float4* wrowA = reinterpret_cast<const float4*>(sW1 + ja * W1S) + qa * 16;
    const float4* hA = reinterpret_cast<const float4*>(shc) + qa * 16;        // g0 hc
    const float4* hB = reinterpret_cast<const float4*>(shc + 256) + qa * 16;  // g1 hc

    // phase F constants
    const float4* wpF  = g_Whh4 + tid;  // stride 512 float4 per k4
    const float4* h0F  = reinterpret_cast<const float4*>(shc);
    const float4* h1F  = reinterpret_cast<const float4*>(shc + 256);

    __syncthreads();

    for (int step = 0; step < TT; step++) {
        // ---- A: u[g][j] = hc[g] . W1[j]  (k split 4-way in lanes, shfl reduce)
        {
            float a0 = 0.f, a1 = 0.f, c0 = 0.f, c1 = 0.f;
#pragma unroll
            for (int i = 0; i < 16; i += 2) {
                float4 w  = wrowA[i];
                float4 x  = hA[i];
                float4 y  = hB[i];
                a0 = fmaf(w.x, x.x, fmaf(w.y, x.y, fmaf(w.z, x.z, fmaf(w.w, x.w, a0))));
                a1 = fmaf(w.x, y.x, fmaf(w.y, y.y, fmaf(w.z, y.z, fmaf(w.w, y.w, a1))));
                float4 w2 = wrowA[i + 1];
                float4 x2 = hA[i + 1];
                float4 y2 = hB[i + 1];
                c0 = fmaf(w2.x, x2.x, fmaf(w2.y, x2.y, fmaf(w2.z, x2.z, fmaf(w2.w, x2.w, c0))));
                c1 = fmaf(w2.x, y2.x, fmaf(w2.y, y2.y, fmaf(w2.z, y2.z, fmaf(w2.w, y2.w, c1))));
            }
            float s0 = a0 + c0, s1 = a1 + c1;
            s0 += __shfl_xor_sync(0xffffffffu, s0, 8);
            s0 += __shfl_xor_sync(0xffffffffu, s0, 16);
            s1 += __shfl_xor_sync(0xffffffffu, s1, 8);
            s1 += __shfl_xor_sync(0xffffffffu, s1, 16);
            if (lane < 8) { su[ja] = s0; su[128 + ja] = s1; }
        }
        __syncthreads();

        // ---- B: 64 logits, 4 rows per warp, lane owns 4 h's (float4)
        {
#pragma unroll
            for (int i = 0; i < 4; i++) {
                int p  = warp * 4 + i;
                int pg = p >> 5, pt = p & 31;
                float4 e1 = reinterpret_cast<const float4*>(sE1 + (pg * 32 + pt) * 128)[lane];
                float4 uu = reinterpret_cast<const float4*>(su + pg * 128)[lane];
                float s = fast_tanh(e1.x + uu.x) * w2v.x
                        + fast_tanh(e1.y + uu.y) * w2v.y
                        + fast_tanh(e1.z + uu.z) * w2v.z
                        + fast_tanh(e1.w + uu.w) * w2v.w;
#pragma unroll
                for (int o = 16; o > 0; o >>= 1)
                    s += __shfl_xor_sync(0xffffffffu, s, o);
                if (lane == 0) slog[p] = s;
            }
        }
        __syncthreads();

        // ---- C: softmax over t (warps 0,1 = batch 0,1)
        if (warp < 2) {
            float l  = slog[warp * 32 + lane];
            float mx = l;
#pragma unroll
            for (int o = 16; o > 0; o >>= 1)
                mx = fmaxf(mx, __shfl_xor_sync(0xffffffffu, mx, o));
            float e   = __expf(l - mx);
            float sum = e;
#pragma unroll
            for (int o = 16; o > 0; o >>= 1)
                sum += __shfl_xor_sync(0xffffffffu, sum, o);
            slog[warp * 32 + lane] = e / sum;
        }
        __syncthreads();

        // ---- D: ctx partials, t split 2-way across thread halves
        {
            int j  = tid & 127;
            int gD = (tid >> 7) & 1;
            int th = tid >> 8;
            const float* ag = slog + gD * 32 + th * 16;
            const float* eg = sEnc + gD * 4096 + th * 2048 + j;
            float acc = 0.f;
#pragma unroll
            for (int t = 0; t < 16; t++)
                acc = fmaf(ag[t], eg[t * 128], acc);
            sctx2[th * 256 + gD * 128 + j] = acc;
        }
        __syncthreads();

        // ---- E: y_tilde (warps 0,1)
        if (warp < 2) {
            float4 c0 = reinterpret_cast<const float4*>(sctx2 + warp * 128)[lane];
            float4 c1 = reinterpret_cast<const float4*>(sctx2 + 256 + warp * 128)[lane];
            float4 f  = reinterpret_cast<const float4*>(sfc)[lane];
            float s = (c0.x + c1.x) * f.x + (c0.y + c1.y) * f.y
                    + (c0.z + c1.z) * f.z + (c0.w + c1.w) * f.w;
#pragma unroll
            for (int o = 16; o > 0; o >>= 1)
                s += __shfl_xor_sync(0xffffffffu, s, o);
            if (lane == 0) {
                float yt = yhist[(b0 + warp) * TT + step];
                sY[warp] = s + yt * sfc[128] + fcb[0];
            }
        }
        __syncthreads();

        // ---- F: gates; thread owns row r = tid, both batches, coalesced LDG.128
        {
            float y0 = sY[0], y1 = sY[1];
            float wih = sWih[tid], bs = sbias[tid];
            float a0 = fmaf(y0, wih, bs), a1 = fmaf(y1, wih, bs);
            float d0 = 0.f, d1 = 0.f;
#pragma unroll 8
            for (int k4 = 0; k4 < 32; k4 += 2) {
                float4 w  = wpF[k4 * 512];
                float4 hx = h0F[k4];
                float4 hy = h1F[k4];
                a0 = fmaf(w.x, hx.x, fmaf(w.y, hx.y, fmaf(w.z, hx.z, fmaf(w.w, hx.w, a0))));
                a1 = fmaf(w.x, hy.x, fmaf(w.y, hy.y, fmaf(w.z, hy.z, fmaf(w.w, hy.w, a1))));
                float4 w2  = wpF[(k4 + 1) * 512];
                float4 hx2 = h0F[k4 + 1];
                float4 hy2 = h1F[k4 + 1];
                d0 = fmaf(w2.x, hx2.x, fmaf(w2.y, hx2.y, fmaf(w2.z, hx2.z, fmaf(w2.w, hx2.w, d0))));
                d1 = fmaf(w2.x, hy2.x, fmaf(w2.y, hy2.y, fmaf(w2.z, hy2.z, fmaf(w2.w, hy2.w, d1))));
            }
            sgates[tid]       = a0 + d0;
            sgates[512 + tid] = a1 + d1;
        }
        __syncthreads();

        // ---- G: LSTM cell update (accurate activations for stability)
        if (tid < 256) {
            int gG = tid >> 7, j = tid & 127;
            const float* gg = sgates + gG * 512;
            float gi = gg[j], gf = gg[128 + j], gc = gg[256 + j], go = gg[384 + j];
            float c_old = shc[gG * 256 + 128 + j];
            float si = 1.f / (1.f + expf(-gi));
            float sf = 1.f / (1.f + expf(-gf));
            float so = 1.f / (1.f + expf(-go));
            float cn = sf * c_old + si * tanhf(gc);
            float hn = so * tanhf(cn);
            shc[gG * 256 + 128 + j] = cn;
            shc[gG * 256 + j]       = hn;
        }
        __syncthreads();
    }

    // ---- final: out[b] = [h, ctx] . fcfW + fcfb + y_history[b, T-1]
    if (warp < 2) {
        float4 hv = reinterpret_cast<const float4*>(shc + warp * 256)[lane];
        float4 f1 = reinterpret_cast<const float4*>(sfcf)[lane];
        float4 c0 = reinterpret_cast<const float4*>(sctx2 + warp * 128)[lane];
        float4 c1 = reinterpret_cast<const float4*>(sctx2 + 256 + warp * 128)[lane];
        float4 f2 = reinterpret_cast<const float4*>(sfcf + 128)[lane];
        float s = hv.x * f1.x + hv.y * f1.y + hv.z * f1.z + hv.w * f1.w
                + (c0.x + c1.x) * f2.x + (c0.y + c1.y) * f2.y
                + (c0.z + c1.z) * f2.z + (c0.w + c1.w) * f2.w;
#pragma unroll
        for (int o = 16; o > 0; o >>= 1)
            s += __shfl_xor_sync(0xffffffffu, s, o);
        if (lane == 0)
            out[b0 + warp] = s + fcfb[0] + yhist[(b0 + warp) * TT + (TT - 1)];
    }
}

// ---------------------------------------------------------------------------
extern "C" void kernel_launch(void* const* d_in, const int* in_sizes, int n_in,
                              void* d_out, int out_size)
{
    const float* enc  = (const float*)d_in[0];
    const float* yh   = (const float*)d_in[1];
    const float* W1   = (const float*)d_in[2];
    const float* b1   = (const float*)d_in[3];
    const float* W2   = (const float*)d_in[4];
    // d_in[5] = attn_b2 : constant shift, cancels in softmax
    const float* Wih  = (const float*)d_in[6];
    const float* Whh  = (const float*)d_in[7];
    const float* bih  = (const float*)d_in[8];
    const float* bhh  = (const float*)d_in[9];
    const float* fcW  = (const float*)d_in[10];
    const float* fcb  = (const float*)d_in[11];
    const float* fcfW = (const float*)d_in[12];
    const float* fcfb = (const float*)d_in[13];
    float* out = (float*)d_out;

    const size_t smem_floats = 34304 + 8192 + 8192 + 512 + 256 + 64 + 512
                             + 1024 + 512 + 512 + 132 + 256 + 4;
    const size_t smem = smem_floats * sizeof(float);   // 217,888 B

    cudaFuncSetAttribute(decoder_kernel,
                         cudaFuncAttributeMaxDynamicSharedMemorySize, (int)smem);

    prep_kernel<<<272, 128>>>(enc, W1, b1, Whh);
    decoder_kernel<<<128, 512, smem>>>(enc, yh, W2, Wih, bih, bhh,
                                       fcW, fcb, fcfW, fcfb, out);
}

// round 3
// speedup vs baseline: 1.1727x; 1.1096x over previous
#include <cuda_runtime.h>

#define BB   256
#define TT   32
#define ENCD 128
#define DECD 128

// Device-global scratch
__device__ float  g_E1[BB * TT * ENCD];   // [B][T][128] = enc @ W1e^T + b1
__device__ float  g_W1P[128 * 256];       // [j][k] W1 hc-part, row-major
__device__ float4 g_Whh4[32 * 512];       // [k4][r] : float4 = Whh[r][4k4..4k4+3]

__device__ __forceinline__ float fast_tanh(float x) {
    float y;
    asm("tanh.approx.f32 %0, %1;" : "=f"(y) : "f"(x));
    return y;
}
__device__ __forceinline__ float fast_sig(float x) {
    return 0.5f + 0.5f * fast_tanh(0.5f * x);
}
// interleaved slot for float4 index f (0..63) of the 256-float hc vector
__device__ __forceinline__ int slotf(int f) { return ((f & 15) << 2) | (f >> 4); }

// ---------------------------------------------------------------------------
// Prep: E1 (blocks 0..255), Whh repack (256..263), W1 pack (264..271)
// ---------------------------------------------------------------------------
__global__ void __launch_bounds__(128)
prep_kernel(const float* __restrict__ enc,
            const float* __restrict__ W1,    // [128, 384] cols: [hc(256) | enc(128)]
            const float* __restrict__ b1,
            const float* __restrict__ Whh)   // [512,128]
{
    int bid = blockIdx.x;
    if (bid < BB) {
        __shared__ float enc_s[TT * ENCD];
        const float* eb = enc + bid * TT * ENCD;
        for (int i = threadIdx.x; i < TT * ENCD; i += blockDim.x)
            enc_s[i] = eb[i];
        __syncthreads();
        int h = threadIdx.x;
        float acc[TT];
        float bb = b1[h];
#pragma unroll
        for (int t = 0; t < TT; t++) acc[t] = bb;
        const float4* wrow = reinterpret_cast<const float4*>(W1 + h * 384 + 256);
#pragma unroll 2
        for (int k4 = 0; k4 < ENCD / 4; k4++) {
            float4 w = wrow[k4];
#pragma unroll
            for (int t = 0; t < TT; t++) {
                float4 e = reinterpret_cast<const float4*>(enc_s + t * ENCD)[k4];
                acc[t] += w.x * e.x + w.y * e.y + w.z * e.z + w.w * e.w;
            }
        }
        float* outp = g_E1 + bid * TT * ENCD;
#pragma unroll
        for (int t = 0; t < TT; t++) outp[t * ENCD + h] = acc[t];
    } else if (bid < 264) {
        int base = (bid - 256) * 8192;
        float* dst = reinterpret_cast<float*>(g_Whh4);
        for (int i = base + threadIdx.x; i < base + 8192; i += 128) {
            int k4 = i >> 11;
            int r  = (i >> 2) & 511;
            int m  = i & 3;
            dst[i] = Whh[r * 128 + (k4 << 2) + m];
        }
    } else {
        int jbase = (bid - 264) * 16;
        for (int idx = threadIdx.x; idx < 16 * 256; idx += 128) {
            int j = jbase + (idx >> 8), k = idx & 255;
            g_W1P[j * 256 + k] = W1[j * 384 + k];
        }
    }
}

// ---------------------------------------------------------------------------
// Main: 128 blocks x 512 threads, 2 batches/block
// ---------------------------------------------------------------------------
__global__ void __launch_bounds__(512, 1)
decoder_kernel(const float* __restrict__ enc,
               const float* __restrict__ yhist,
               const float* __restrict__ W2,
               const float* __restrict__ Wih,
               const float* __restrict__ bih,
               const float* __restrict__ bhh,
               const float* __restrict__ fcW,
               const float* __restrict__ fcb,
               const float* __restrict__ fcfW,
               const float* __restrict__ fcfb,
               float* __restrict__ out)
{
    extern __shared__ float sm[];
    float* sE1   = sm;                // 8192 [g][t][128]
    float* sEnc  = sE1 + 8192;        // 8192 [g][t][128]
    float* sgp   = sEnc + 8192;       // 2048 [kh][g][512] gate partials
    float* sHC   = sgp + 2048;        // 512  [g][256] quarter-interleaved hc
    float* su    = sHC + 512;         // 256  [g][128]
    float* sctx2 = su + 256;          // 512  [th][g][128]
    float* sWih  = sctx2 + 512;       // 512
    float* sbias = sWih + 512;        // 512
    float* sfcf  = sbias + 512;       // 256
    float* sW2   = sfcf + 256;        // 128
    float* sfc   = sW2 + 128;         // 132 (129 used + fcb at [129])
    float* slog  = sfc + 132;         // 64
    float* sY    = slog + 64;         // 4

    const int tid  = threadIdx.x;
    const int lane = tid & 31;
    const int warp = tid >> 5;
    const int bp   = blockIdx.x * 2;

    // ---- persistent W1 registers: thread (ja, qa) holds W1[ja][qa*64..+63]
    const int qa = lane >> 3;
    const int ja = (warp << 3) | (lane & 7);
    float4 w1r[16];
#pragma unroll
    for (int i = 0; i < 16; i++)
        w1r[i] = reinterpret_cast<const float4*>(g_W1P)[ja * 64 + qa * 16 + i];

    // ---- load phase ----
    for (int i = tid; i < 2048; i += 512) {
        reinterpret_cast<float4*>(sE1)[i] =
            reinterpret_cast<const float4*>(g_E1 + (size_t)bp * TT * ENCD)[i];
        reinterpret_cast<float4*>(sEnc)[i] =
            reinterpret_cast<const float4*>(enc + (size_t)bp * TT * ENCD)[i];
    }
    sWih[tid]  = Wih[tid];
    sbias[tid] = bih[tid] + bhh[tid];
    sHC[tid]   = 0.f;
    if (tid < 128) sW2[tid]  = W2[tid];
    if (tid < 256) sfcf[tid] = fcfW[tid];
    if (tid < 130) sfc[tid]  = (tid < 129) ? fcW[tid] : fcb[0];

    // phase F coords: warps 0-7 -> kh=0 (L1-pinned half), 8-15 -> kh=1 (L2)
    const int kh = warp >> 3;
    const int rr = ((warp & 7) << 5) | lane;   // 0..255
    const float4* wbF = g_Whh4 + (kh << 4) * 512;

    __syncthreads();

    for (int step = 0; step < TT; step++) {
        // ---- A: u[g][ja] = hc[g] . W1[ja], k quarter per thread, shfl-reduce
        {
            const float4* h0 = reinterpret_cast<const float4*>(sHC);
            const float4* h1 = reinterpret_cast<const float4*>(sHC + 256);
            float a0 = 0.f, a1 = 0.f, b0 = 0.f, b1 = 0.f;
#pragma unroll
            for (int i = 0; i < 16; i += 2) {
                float4 w = w1r[i];
                float4 x = h0[(i << 2) | qa];
                float4 y = h1[(i << 2) | qa];
                a0 = fmaf(w.x, x.x, fmaf(w.y, x.y, fmaf(w.z, x.z, fmaf(w.w, x.w, a0))));
                a1 = fmaf(w.x, y.x, fmaf(w.y, y.y, fmaf(w.z, y.z, fmaf(w.w, y.w, a1))));
                float4 w2 = w1r[i + 1];
                float4 x2 = h0[((i + 1) << 2) | qa];
                float4 y2 = h1[((i + 1) << 2) | qa];
                b0 = fmaf(w2.x, x2.x, fmaf(w2.y, x2.y, fmaf(w2.z, x2.z, fmaf(w2.w, x2.w, b0))));
                b1 = fmaf(w2.x, y2.x, fmaf(w2.y, y2.y, fmaf(w2.z, y2.z, fmaf(w2.w, y2.w, b1))));
            }
            float s0 = a0 + b0, s1 = a1 + b1;
            s0 += __shfl_xor_sync(0xffffffffu, s0, 8);
            s0 += __shfl_xor_sync(0xffffffffu, s0, 16);
            s1 += __shfl_xor_sync(0xffffffffu, s1, 8);
            s1 += __shfl_xor_sync(0xffffffffu, s1, 16);
            if (lane < 8) { su[ja] = s0; su[128 + ja] = s1; }
        }
        __syncthreads();

        // ---- B: 64 logits; warp covers 4 rows via 8-lane groups
        {
            int c8 = lane & 7;
            int p  = (warp << 2) | (lane >> 3);
            int pg = p >> 5, pt = p & 31;
            const float4* e1r = reinterpret_cast<const float4*>(sE1 + (pg * 32 + pt) * 128);
            const float4* ur  = reinterpret_cast<const float4*>(su + pg * 128);
            const float4* w2r = reinterpret_cast<const float4*>(sW2);
            float s = 0.f;
#pragma unroll
            for (int c = 0; c < 4; c++) {
                float4 e = e1r[c8 * 4 + c];
                float4 u = ur[c8 * 4 + c];
                float4 w = w2r[c8 * 4 + c];
                s += fast_tanh(e.x + u.x) * w.x + fast_tanh(e.y + u.y) * w.y
                   + fast_tanh(e.z + u.z) * w.z + fast_tanh(e.w + u.w) * w.w;
            }
            s += __shfl_xor_sync(0xffffffffu, s, 1);
            s += __shfl_xor_sync(0xffffffffu, s, 2);
            s += __shfl_xor_sync(0xffffffffu, s, 4);
            if (c8 == 0) slog[p] = s;
        }
        __syncthreads();

        // ---- C: softmax (warps 0,1 = batch 0,1)
        if (warp < 2) {
            float l  = slog[warp * 32 + lane];
            float mx = l;
#pragma unroll
            for (int o = 16; o > 0; o >>= 1)
                mx = fmaxf(mx, __shfl_xor_sync(0xffffffffu, mx, o));
            float e   = __expf(l - mx);
            float sum = e;
#pragma unroll
            for (int o = 16; o > 0; o >>= 1)
                sum += __shfl_xor_sync(0xffffffffu, sum, o);
            slog[warp * 32 + lane] = e / sum;
        }
        __syncthreads();

        // ---- D: ctx partials, t split 2-way
        {
            int j = tid & 127, gD = (tid >> 7) & 1, th = tid >> 8;
            const float* ag = slog + gD * 32 + th * 16;
            const float* eg = sEnc + gD * 4096 + th * 2048 + j;
            float acc = 0.f;
#pragma unroll
            for (int t = 0; t < 16; t++)
                acc = fmaf(ag[t], eg[t * 128], acc);
            sctx2[th * 256 + gD * 128 + j] = acc;
        }
        __syncthreads();

        // ---- E: y_tilde (warps 0,1)
        if (warp < 2) {
            float4 c0 = reinterpret_cast<const float4*>(sctx2 + warp * 128)[lane];
            float4 c1 = reinterpret_cast<const float4*>(sctx2 + 256 + warp * 128)[lane];
            float4 f  = reinterpret_cast<const float4*>(sfc)[lane];
            float s = (c0.x + c1.x) * f.x + (c0.y + c1.y) * f.y
                    + (c0.z + c1.z) * f.z + (c0.w + c1.w) * f.w;
#pragma unroll
            for (int o = 16; o > 0; o >>= 1)
                s += __shfl_xor_sync(0xffffffffu, s, o);
            if (lane == 0) {
                float yt = yhist[(bp + warp) * TT + step];
                sY[warp] = s + yt * sfc[128] + sfc[129];
            }
        }
        __syncthreads();

        // ---- F: gate partials. Thread: rows {rr, rr+256}, k-half kh, 2 batches.
        {
            const float4* h0 = reinterpret_cast<const float4*>(sHC);
            const float4* h1 = reinterpret_cast<const float4*>(sHC + 256);
            float A00 = 0.f, A01 = 0.f, A10 = 0.f, A11 = 0.f;
            float B00 = 0.f, B01 = 0.f, B10 = 0.f, B11 = 0.f;
#pragma unroll
            for (int m = 0; m < 16; m += 2) {
                int k4a = (kh << 4) | m;
                float4 wa0, wa1, wb0, wb1;
                if (kh == 0) {
                    wa0 = __ldca(wbF + m * 512 + rr);
                    wa1 = __ldca(wbF + m * 512 + rr + 256);
                    wb0 = __ldca(wbF + (m + 1) * 512 + rr);
                    wb1 = __ldca(wbF + (m + 1) * 512 + rr + 256);
                } else {
                    wa0 = __ldcg(wbF + m * 512 + rr);
                    wa1 = __ldcg(wbF + m * 512 + rr + 256);
                    wb0 = __ldcg(wbF + (m + 1) * 512 + rr);
                    wb1 = __ldcg(wbF + (m + 1) * 512 + rr + 256);
                }
                float4 hx = h0[slotf(k4a)];
                float4 hy = h1[slotf(k4a)];
                float4 hx2 = h0[slotf(k4a + 1)];
                float4 hy2 = h1[slotf(k4a + 1)];
                A00 = fmaf(wa0.x, hx.x, fmaf(wa0.y, hx.y, fmaf(wa0.z, hx.z, fmaf(wa0.w, hx.w, A00))));
                A01 = fmaf(wa0.x, hy.x, fmaf(wa0.y, hy.y, fmaf(wa0.z, hy.z, fmaf(wa0.w, hy.w, A01))));
                A10 = fmaf(wa1.x, hx.x, fmaf(wa1.y, hx.y, fmaf(wa1.z, hx.z, fmaf(wa1.w, hx.w, A10))));
                A11 = fmaf(wa1.x, hy.x, fmaf(wa1.y, hy.y, fmaf(wa1.z, hy.z, fmaf(wa1.w, hy.w, A11))));
                B00 = fmaf(wb0.x, hx2.x, fmaf(wb0.y, hx2.y, fmaf(wb0.z, hx2.z, fmaf(wb0.w, hx2.w, B00))));
                B01 = fmaf(wb0.x, hy2.x, fmaf(wb0.y, hy2.y, fmaf(wb0.z, hy2.z, fmaf(wb0.w, hy2.w, B01))));
                B10 = fmaf(wb1.x, hx2.x, fmaf(wb1.y, hx2.y, fmaf(wb1.z, hx2.z, fmaf(wb1.w, hx2.w, B10))));
                B11 = fmaf(wb1.x, hy2.x, fmaf(wb1.y, hy2.y, fmaf(wb1.z, hy2.z, fmaf(wb1.w, hy2.w, B11))));
            }
            float* P = sgp + (kh << 10);
            P[rr]             = A00 + B00;
            P[512 + rr]       = A01 + B01;
            P[rr + 256]       = A10 + B10;
            P[512 + rr + 256] = A11 + B11;
        }
        __syncthreads();

        // ---- G: combine partials + LSTM cell (fast activations)
        if (tid < 256) {
            int j = tid & 127, g = tid >> 7;
            float y = sY[g];
            const float* P0 = sgp + g * 512;
            const float* P1 = sgp + 1024 + g * 512;
            float gv[4];
#pragma unroll
            for (int q = 0; q < 4; q++) {
                int r = q * 128 + j;
                gv[q] = P0[r] + P1[r] + sbias[r] + y * sWih[r];
            }
            int fc_ = 32 + (j >> 2);
            int sc  = ((fc_ & 15) << 2) | (fc_ >> 4);
            int fh  = j >> 2;
            int sh  = ((fh & 15) << 2) | (fh >> 4);
            float c_old = sHC[g * 256 + sc * 4 + (j & 3)];
            float si = fast_sig(gv[0]);
            float sf = fast_sig(gv[1]);
            float so = fast_sig(gv[3]);
            float cn = sf * c_old + si * fast_tanh(gv[2]);
            float hn = so * fast_tanh(cn);
            sHC[g * 256 + sc * 4 + (j & 3)] = cn;
            sHC[g * 256 + sh * 4 + (j & 3)] = hn;
        }
        __syncthreads();
    }

    // ---- final: out[b] = [h, ctx] . fcfW + fcfb + y_history[b, T-1]
    if (warp < 2) {
        float4 hv = reinterpret_cast<const float4*>(sHC + warp * 256)[slotf(lane)];
        float4 f1 = reinterpret_cast<const float4*>(sfcf)[lane];
        float4 c0 = reinterpret_cast<const float4*>(sctx2 + warp * 128)[lane];
        float4 c1 = reinterpret_cast<const float4*>(sctx2 + 256 + warp * 128)[lane];
        float4 f2 = reinterpret_cast<const float4*>(sfcf + 128)[lane];
        float s = hv.x * f1.x + hv.y * f1.y + hv.z * f1.z + hv.w * f1.w
                + (c0.x + c1.x) * f2.x + (c0.y + c1.y) * f2.y
                + (c0.z + c1.z) * f2.z + (c0.w + c1.w) * f2.w;
#pragma unroll
        for (int o = 16; o > 0; o >>= 1)
            s += __shfl_xor_sync(0xffffffffu, s, o);
        if (lane == 0)
            out[bp + warp] = s + fcfb[0] + yhist[(bp + warp) * TT + (TT - 1)];
    }
}

// ---------------------------------------------------------------------------
extern "C" void kernel_launch(void* const* d_in, const int* in_sizes, int n_in,
                              void* d_out, int out_size)
{
    const float* enc  = (const float*)d_in[0];
    const float* yh   = (const float*)d_in[1];
    const float* W1   = (const float*)d_in[2];
    const float* b1   = (const float*)d_in[3];
    const float* W2   = (const float*)d_in[4];
    // d_in[5] = attn_b2 : cancels in softmax
    const float* Wih  = (const float*)d_in[6];
    const float* Whh  = (const float*)d_in[7];
    const float* bih  = (const float*)d_in[8];
    const float* bhh  = (const float*)d_in[9];
    const float* fcW  = (const float*)d_in[10];
    const float* fcb  = (const float*)d_in[11];
    const float* fcfW = (const float*)d_in[12];
    const float* fcfb = (const float*)d_in[13];
    float* out = (float*)d_out;

    const size_t smem_floats = 8192 + 8192 + 2048 + 512 + 256 + 512
                             + 512 + 512 + 256 + 128 + 132 + 64 + 4;
    const size_t smem = smem_floats * sizeof(float);   // ~85.3 KB

    cudaFuncSetAttribute(decoder_kernel,
                         cudaFuncAttributeMaxDynamicSharedMemorySize, (int)smem);
    // hint: minimize smem carveout so ~143KB of L1D holds the kh=0 Whh half
    cudaFuncSetAttribute(decoder_kernel,
                         cudaFuncAttributePreferredSharedMemoryCarveout, 38);

    prep_kernel<<<272, 128>>>(enc, W1, b1, Whh);
    decoder_kernel<<<128, 512, smem>>>(enc, yh, W2, Wih, bih, bhh,
                                       fcW, fcb, fcfW, fcfb, out);
}